// round 17
// baseline (speedup 1.0000x reference)
#include <cuda_runtime.h>

#define KCLS 19
#define NIMG 4
#define CDIM 128
#define PPIX 131072   // 256*512
#define NB   1036     // persistent grid: 7 blocks/SM on 148 SMs (all co-resident)
#define NT   256

#define P1_ITEMS 8192   // 8K px of one channel: 4*128*16
#define P2_ITEMS 4096   // 128 px: 4 * 1024

// Scratch (device globals; no allocation allowed)
__device__ unsigned char g_lab[NIMG * PPIX];
__device__ float g_sums[NIMG * KCLS * CDIM];
__device__ int   g_hist[256 * 20];          // per-prep-item partial histograms
__device__ float g_rsum[NIMG * KCLS];
__device__ int   g_work[2];                 // stealing counters (re-zeroed in phase 0)
__device__ int   g_barcnt;                  // zero-init, returns to 0 after each barrier
__device__ int   g_bargen;                  // monotone generation counter

// Global barrier: sense-reversal via generation counter. Requires all NB
// blocks co-resident (enforced by __launch_bounds__(NT,7), grid=7*148).
__device__ __forceinline__ void gbar() {
    __syncthreads();
    if (threadIdx.x == 0) {
        __threadfence();
        int gen = *(volatile int*)&g_bargen;
        if (atomicAdd(&g_barcnt, 1) == NB - 1) {
            atomicExch(&g_barcnt, 0);
            __threadfence();
            atomicAdd(&g_bargen, 1);
        } else {
            while (*(volatile int*)&g_bargen == gen) __nanosleep(64);
        }
        __threadfence();
    }
    __syncthreads();
}

// Shared-memory union: phase1 acc[20*256]=20480B; phase2/3 tables ~11KB.
#define SM_BYTES 20992
#define OFF_MS    0        // float ms[2432]   (one image: [c][k])
#define OFF_INV   9728     // float inv[80]
#define OFF_SCNT  10048    // int   scnt[80]
#define OFF_RPART 10368    // float rpart[19]
#define OFF_SSC   10448    // float ssc[3]
#define OFF_SA    10464    // float sa[128] (phase-2 half-combine)
#define OFF_ITEM  20480    // int (beyond phase-1 acc region)

__global__ void __launch_bounds__(NT, 7)
k_all(const float* __restrict__ x, const void* __restrict__ tgt,
      const int* __restrict__ t32, float* __restrict__ out) {
    __shared__ __align__(16) char smraw[SM_BYTES];
    const int tid = threadIdx.x;
    const int bid = blockIdx.x;
    int* s_item = (int*)(smraw + OFF_ITEM);

    // dtype detect, redundantly per block (int64 labels<19 => odd words all 0)
    int w = t32[tid * 2 + 1];
    int is64 = __syncthreads_and(w == 0);

    // ================= phase 0: labels + histograms + zeroing =================
    if (bid < 256) {
        int* h = (int*)smraw;
        if (tid < 20) h[tid] = 0;
        __syncthreads();
        int n = bid >> 6, blk = bid & 63;
        unsigned char* lp = g_lab + (size_t)n * PPIX;
        #pragma unroll
        for (int it = 0; it < 2; ++it) {
            int p = blk * 2048 + it * 1024 + tid * 4;
            int v0, v1, v2, v3;
            if (is64) {
                const long long* tp = (const long long*)tgt + (size_t)n * PPIX;
                longlong2 a = *(const longlong2*)(tp + p);
                longlong2 b = *(const longlong2*)(tp + p + 2);
                v0 = (int)a.x; v1 = (int)a.y; v2 = (int)b.x; v3 = (int)b.y;
            } else {
                const int* tp = (const int*)tgt + (size_t)n * PPIX;
                int4 a = *(const int4*)(tp + p);
                v0 = a.x; v1 = a.y; v2 = a.z; v3 = a.w;
            }
            uchar4 u;
            u.x = (v0 >= 0 && v0 < KCLS) ? (unsigned char)v0 : (unsigned char)255;
            u.y = (v1 >= 0 && v1 < KCLS) ? (unsigned char)v1 : (unsigned char)255;
            u.z = (v2 >= 0 && v2 < KCLS) ? (unsigned char)v2 : (unsigned char)255;
            u.w = (v3 >= 0 && v3 < KCLS) ? (unsigned char)v3 : (unsigned char)255;
            *(uchar4*)(lp + p) = u;
            atomicAdd(&h[u.x < KCLS ? (int)u.x : 19], 1);
            atomicAdd(&h[u.y < KCLS ? (int)u.y : 19], 1);
            atomicAdd(&h[u.z < KCLS ? (int)u.z : 19], 1);
            atomicAdd(&h[u.w < KCLS ? (int)u.w : 19], 1);
        }
        __syncthreads();
        if (tid < 20) g_hist[bid * 20 + tid] = h[tid];
    } else if (bid < 294) {
        int idx = (bid - 256) * 256 + tid;
        if (idx < NIMG * KCLS * CDIM) g_sums[idx] = 0.f;
    } else if (bid == 294) {
        if (tid < NIMG * KCLS) g_rsum[tid] = 0.f;
        if (tid >= 128 && tid < 130) g_work[tid - 128] = 0;
    }
    gbar();

    // ================= phase 1: segment sums (work-stealing) =================
    // item: 8192 px of one channel. item = (n<<11) | (c<<4) | chunk
    {
        float* acc = (float*)smraw;   // [20][256]
        for (;;) {
            if (tid == 0) *s_item = atomicAdd(&g_work[0], 1);
            __syncthreads();                 // also orders prev reduce before re-zero
            int item = *s_item;
            if (item >= P1_ITEMS) break;
            int n = item >> 11, c = (item >> 4) & 127, chunk = item & 15;
            #pragma unroll
            for (int k = 0; k < 20; ++k) acc[k * 256 + tid] = 0.f;
            __syncthreads();

            const float4* xp = (const float4*)(x + ((size_t)(n * CDIM + c)) * PPIX + (size_t)chunk * 8192);
            const uchar4* lp = (const uchar4*)(g_lab + (size_t)n * PPIX + (size_t)chunk * 8192);
            #pragma unroll 4
            for (int i = tid; i < 2048; i += 256) {
                float4 v = xp[i];
                uchar4 l = lp[i];
                int k0 = l.x < KCLS ? (int)l.x : 19;
                int k1 = l.y < KCLS ? (int)l.y : 19;
                int k2 = l.z < KCLS ? (int)l.z : 19;
                int k3 = l.w < KCLS ? (int)l.w : 19;
                acc[k0 * 256 + tid] += v.x;
                acc[k1 * 256 + tid] += v.y;
                acc[k2 * 256 + tid] += v.z;
                acc[k3 * 256 + tid] += v.w;
            }
            __syncthreads();

            int warp = tid >> 5, lane = tid & 31;
            for (int k = warp; k < KCLS; k += 8) {
                float s = 0.f;
                #pragma unroll
                for (int j = 0; j < 8; ++j) s += acc[k * 256 + j * 32 + lane];
                #pragma unroll
                for (int o = 16; o > 0; o >>= 1) s += __shfl_down_sync(0xffffffffu, s, o);
                if (lane == 0) atomicAdd(&g_sums[(n * KCLS + k) * CDIM + c], s);
            }
        }
    }
    gbar();

    // ================= phase 2: per-pixel variance term (work-stealing) =====
    float* ms    = (float*)(smraw + OFF_MS);     // one image, [c][k]
    float* inv   = (float*)(smraw + OFF_INV);
    int*   scnt  = (int*)  (smraw + OFF_SCNT);
    float* rpart = (float*)(smraw + OFF_RPART);
    float* ssc   = (float*)(smraw + OFF_SSC);
    float* sa    = (float*)(smraw + OFF_SA);

    if (tid < 80) {
        int n = tid / 20, k = tid % 20, sum = 0;
        #pragma unroll 4
        for (int b = 0; b < 64; ++b) sum += g_hist[(n * 64 + b) * 20 + k];
        scnt[tid] = sum;
        inv[tid] = 1.0f / fmaxf((float)sum, 1.f);
    }
    __syncthreads();

    // item: 128 px of one image; warps 0-3 handle channels [0,64), 4-7 [64,128)
    {
        int cur_n = -1;
        const int wrp = tid >> 5, lane = tid & 31;
        const int pxl = (wrp & 3) * 32 + lane;   // 0..127
        const int half = wrp >> 2;               // 0 or 1
        for (;;) {
            if (tid == 0) *s_item = atomicAdd(&g_work[1], 1);
            __syncthreads();
            int item = *s_item;
            if (item >= P2_ITEMS) break;
            int n = item >> 10, t = item & 1023;
            if (n != cur_n) {
                for (int i = tid; i < CDIM * KCLS; i += 256) {
                    int c = i / KCLS, k = i % KCLS;
                    ms[i] = g_sums[(n * KCLS + k) * CDIM + c] * inv[n * 20 + k];
                }
                cur_n = n;
                __syncthreads();
            }
            if (tid < KCLS) rpart[tid] = 0.f;

            int px = t * 128 + pxl;
            int lb = g_lab[(size_t)n * PPIX + px];
            int b = lb < KCLS ? lb : 0;
            const float* xp = x + ((size_t)(n * CDIM + half * 64)) * PPIX + px;
            const float* mc = ms + half * 64 * KCLS + b;
            float a = 0.f;
            #pragma unroll 8
            for (int c = 0; c < 64; ++c) {
                float v = xp[(size_t)c * PPIX];
                float d = mc[c * KCLS] - v;
                a = fmaf(d, d, a);
            }
            if (half == 0) sa[pxl] = a;
            __syncthreads();
            if (half == 1) {
                float full = a + sa[pxl];
                float r = fmaxf(sqrtf(full) - 0.5f, 0.f); r *= r;
                if (lb < KCLS) atomicAdd(&rpart[lb], r);
            }
            __syncthreads();
            if (tid < KCLS && rpart[tid] != 0.f) atomicAdd(&g_rsum[n * KCLS + tid], rpart[tid]);
        }
    }
    gbar();

    // ================= phase 3: final scalar (block 0 only) =================
    if (bid == 0) {
        float total = 0.f;   // meaningful on tid 0 only
        for (int n = 0; n < NIMG; ++n) {
            // rebuild this image's means table
            for (int i = tid; i < CDIM * KCLS; i += 256) {
                int c = i / KCLS, k = i % KCLS;
                ms[i] = g_sums[(n * KCLS + k) * CDIM + c] * inv[n * 20 + k];
            }
            if (tid == 0) { ssc[0] = 0.f; ssc[1] = 0.f; ssc[2] = 0.f; }
            __syncthreads();

            if (tid < KCLS) {
                int cnt = scnt[n * 20 + tid];
                if (cnt > 20) {
                    atomicAdd(&ssc[0], g_rsum[n * KCLS + tid] / (float)cnt);
                    float nr = 0.f;
                    #pragma unroll 4
                    for (int c = 0; c < CDIM; ++c) {
                        float mv = ms[c * KCLS + tid];
                        nr = fmaf(mv, mv, nr);
                    }
                    atomicAdd(&ssc[2], sqrtf(nr));
                }
            }
            for (int idx = tid; idx < KCLS * KCLS; idx += 256) {
                int f = idx / KCLS, s = idx % KCLS;
                if (f != s && scnt[n * 20 + f] > 20 && scnt[n * 20 + s] > 20) {
                    float d2 = 0.f;
                    #pragma unroll 4
                    for (int c = 0; c < CDIM; ++c) {
                        float d = ms[c * KCLS + f] - ms[c * KCLS + s];
                        d2 = fmaf(d, d, d2);
                    }
                    float t = fmaxf(3.0f - sqrtf(d2), 0.f);   // 2*DELTA = 3.0
                    atomicAdd(&ssc[1], t * t);
                }
            }
            __syncthreads();

            if (tid == 0) {
                int nvi = 0;
                for (int k = 0; k < KCLS; ++k) nvi += (scnt[n * 20 + k] > 20);
                float nv = fmaxf((float)nvi, 1.f);
                float connect = fmaxf(nv * (nv - 1.f), 1.f);
                total += ssc[0] / nv + ssc[1] / connect + 0.001f * ssc[2] / nv;
            }
            __syncthreads();
        }
        if (tid == 0) out[0] = total * 0.25f;
    }
}

// ---------------------------------------------------------------------------
extern "C" void kernel_launch(void* const* d_in, const int* in_sizes, int n_in,
                              void* d_out, int out_size) {
    int pi = 0, ti = 1;
    if (n_in >= 2 && in_sizes[0] == NIMG * PPIX) { pi = 1; ti = 0; }  // robustness vs input order
    const float* predict = (const float*)d_in[pi];
    const void* target = (const void*)d_in[ti];
    float* out = (float*)d_out;

    k_all<<<NB, NT>>>(predict, target, (const int*)target, out);
}